// round 1
// baseline (speedup 1.0000x reference)
#include <cuda_runtime.h>

#define B_ 1024
#define T_ 512
#define C_ 48
#define NTH 64
#define ROW4 (C_ / 4)   // 12 float4 per row

// Viterbi decode: one block per batch element, one thread per state j.
// Forward: score recurrence with backpointers kept in shared memory.
// Backward: single-thread LDS pointer chase (cheap: ~30 cyc/step).
// Output: fused coalesced one-hot write.
__global__ void __launch_bounds__(NTH, 8)
viterbi_kernel(const float* __restrict__ pot,
               const int* __restrict__ seqlen,
               const float* __restrict__ trans,
               float* __restrict__ out)
{
    __shared__ unsigned char bp_sh[T_ * C_];          // 24576 B backpointers
    __shared__ unsigned char tag_sh[T_];              // decoded tags
    __shared__ __align__(16) float sc[2][C_];         // double-buffered score
    __shared__ int last_tag_sh;

    const int b = blockIdx.x;
    const int j = threadIdx.x;
    const int L = seqlen[b];                          // 1 <= L < T_
    const float* potb = pot + (size_t)b * T_ * C_;

    // trans column j in registers (48 regs/thread)
    float tr[C_];
    if (j < C_) {
#pragma unroll
        for (int i = 0; i < C_; ++i) tr[i] = trans[i * C_ + j];
        sc[0][j] = potb[j];                            // init score = potentials[:,0]
    }
    __syncthreads();

    // ---------------- forward pass ----------------
    int cur = 0;
    float pot_next = (j < C_ && L > 1) ? potb[C_ + j] : 0.0f;  // prefetch t=1
    for (int t = 1; t < L; ++t) {
        const float potc = pot_next;
        if (j < C_ && (t + 1) < L) pot_next = potb[(size_t)(t + 1) * C_ + j];

        if (j < C_) {
            const float4* sv = (const float4*)sc[cur];
            // strict first-index argmax over i of score[i] + trans[i][j]
            float4 q = sv[0];
            float best = q.x + tr[0];
            int bi = 0;
            float v;
            v = q.y + tr[1]; if (v > best) { best = v; bi = 1; }
            v = q.z + tr[2]; if (v > best) { best = v; bi = 2; }
            v = q.w + tr[3]; if (v > best) { best = v; bi = 3; }
#pragma unroll
            for (int i4 = 1; i4 < ROW4; ++i4) {
                q = sv[i4];
                const int ib = i4 * 4;
                v = q.x + tr[ib + 0]; if (v > best) { best = v; bi = ib + 0; }
                v = q.y + tr[ib + 1]; if (v > best) { best = v; bi = ib + 1; }
                v = q.z + tr[ib + 2]; if (v > best) { best = v; bi = ib + 2; }
                v = q.w + tr[ib + 3]; if (v > best) { best = v; bi = ib + 3; }
            }
            bp_sh[t * C_ + j] = (unsigned char)bi;
            sc[cur ^ 1][j] = best + potc;
        }
        __syncthreads();
        cur ^= 1;
    }

    // ---------------- final argmax + backtrack ----------------
    if (j == 0) {
        const float* fs = sc[cur];
        float best = fs[0];
        int bt = 0;
#pragma unroll
        for (int k = 1; k < C_; ++k) {
            float v = fs[k];
            if (v > best) { best = v; bt = k; }
        }
        last_tag_sh = bt;
    }
    __syncthreads();

    const int lt = last_tag_sh;
    // tags[L-1 .. T-1] == last_tag (identity backpointers past seq end)
    for (int t = L - 1 + j; t < T_; t += NTH) tag_sh[t] = (unsigned char)lt;

    if (j == 0) {
        // tags[t-1] = bp[t][tags[t]], t = L-1 .. 1
        int tag = lt;
        for (int t = L - 1; t >= 1; --t) {
            tag = bp_sh[t * C_ + tag];
            tag_sh[t - 1] = (unsigned char)tag;
        }
    }
    __syncthreads();

    // ---------------- fused one-hot output ----------------
    float4* ob = (float4*)(out + (size_t)b * T_ * C_);
    for (int idx = j; idx < T_ * ROW4; idx += NTH) {
        const int t  = idx / ROW4;
        const int qq = idx - t * ROW4;
        const int tg = tag_sh[t];
        const int base = qq * 4;
        float4 v;
        v.x = (tg == base + 0) ? 1.0f : 0.0f;
        v.y = (tg == base + 1) ? 1.0f : 0.0f;
        v.z = (tg == base + 2) ? 1.0f : 0.0f;
        v.w = (tg == base + 3) ? 1.0f : 0.0f;
        ob[idx] = v;
    }
}

extern "C" void kernel_launch(void* const* d_in, const int* in_sizes, int n_in,
                              void* d_out, int out_size)
{
    const float* pot    = (const float*)d_in[0];   // (B, T, C) float32
    const int*   slen   = (const int*)d_in[1];     // (B, 1)    int32
    const float* trans  = (const float*)d_in[2];   // (C, C)    float32
    float*       out    = (float*)d_out;           // (B, T, C) float32

    viterbi_kernel<<<B_, NTH>>>(pot, slen, trans, out);
}

// round 2
// speedup vs baseline: 1.2368x; 1.2368x over previous
#include <cuda_runtime.h>

#define B_ 1024
#define T_ 512
#define C_ 48
#define HALF 24            // i-elements per thread (2-way split of i)
#define NTH 96             // 48 states x 2 halves, 3 full warps
#define ROW4 (C_ / 4)      // 12 float4 per output row

// Viterbi decode: one block per batch element.
// Thread (j,h): j = tid>>1 (state column), h = tid&1 (which half of i).
// Each thread does a first-index argmax over its 24-element half, then the
// lane pair combines via shfl_xor(1) — exact tie-break (lo half = smaller i).
// Backpointers stay in shared; backtrack is a cheap LDS pointer chase.
__global__ void __launch_bounds__(NTH, 8)
viterbi_kernel(const float* __restrict__ pot,
               const int* __restrict__ seqlen,
               const float* __restrict__ trans,
               float* __restrict__ out)
{
    __shared__ unsigned char bp_sh[T_ * C_];          // 24576 B backpointers
    __shared__ unsigned char tag_sh[T_];              // decoded tags
    __shared__ __align__(16) float sc[2][C_];         // double-buffered score
    __shared__ int last_tag_sh;

    const int b   = blockIdx.x;
    const int tid = threadIdx.x;
    const int j   = tid >> 1;                         // state column 0..47
    const int h   = tid & 1;                          // half 0..1
    const int L   = seqlen[b];                        // 1 <= L < T_
    const float* potb = pot + (size_t)b * T_ * C_;

    // trans rows [h*24, h*24+24) of column j, in registers
    float tr[HALF];
#pragma unroll
    for (int k = 0; k < HALF; ++k) tr[k] = trans[(h * HALF + k) * C_ + j];

    if (h == 0) sc[0][j] = potb[j];                   // init score = potentials[:,0]
    __syncthreads();

    // ---------------- forward pass ----------------
    int cur = 0;
    float pot_next = (L > 1) ? potb[C_ + j] : 0.0f;   // prefetch t=1 (broadcast per pair)
    for (int t = 1; t < L; ++t) {
        const float potc = pot_next;
        if (t + 1 < L) pot_next = potb[(size_t)(t + 1) * C_ + j];

        // first-index argmax over this thread's 24-element half
        const float4* sv = (const float4*)(sc[cur] + h * HALF);
        float4 q = sv[0];
        float best = q.x + tr[0];
        int bi = 0;
        float v;
        v = q.y + tr[1]; if (v > best) { best = v; bi = 1; }
        v = q.z + tr[2]; if (v > best) { best = v; bi = 2; }
        v = q.w + tr[3]; if (v > best) { best = v; bi = 3; }
#pragma unroll
        for (int i4 = 1; i4 < HALF / 4; ++i4) {
            q = sv[i4];
            const int ib = i4 * 4;
            v = q.x + tr[ib + 0]; if (v > best) { best = v; bi = ib + 0; }
            v = q.y + tr[ib + 1]; if (v > best) { best = v; bi = ib + 1; }
            v = q.z + tr[ib + 2]; if (v > best) { best = v; bi = ib + 2; }
            v = q.w + tr[ib + 3]; if (v > best) { best = v; bi = ib + 3; }
        }
        // combine halves within the lane pair (exact: ties -> lo half = smaller i)
        const float obest = __shfl_xor_sync(0xFFFFFFFFu, best, 1);
        const int   obi   = __shfl_xor_sync(0xFFFFFFFFu, bi,   1);
        float vlo, vhi; int ilo, ihi;
        if (h == 0) { vlo = best;  ilo = bi;              vhi = obest; ihi = obi + HALF; }
        else        { vlo = obest; ilo = obi;             vhi = best;  ihi = bi + HALF; }
        const float wbest = (vhi > vlo) ? vhi : vlo;
        const int   wbi   = (vhi > vlo) ? ihi : ilo;

        if (h == 0) {
            bp_sh[t * C_ + j] = (unsigned char)wbi;
            sc[cur ^ 1][j] = wbest + potc;
        }
        __syncthreads();
        cur ^= 1;
    }

    // ---------------- final argmax + backtrack ----------------
    if (tid == 0) {
        const float* fs = sc[cur];
        float best = fs[0];
        int bt = 0;
#pragma unroll
        for (int k = 1; k < C_; ++k) {
            float v = fs[k];
            if (v > best) { best = v; bt = k; }
        }
        last_tag_sh = bt;
    }
    __syncthreads();

    const int lt = last_tag_sh;
    // tags[L-1 .. T-1] == last_tag (identity backpointers past seq end)
    for (int t = L - 1 + tid; t < T_; t += NTH) tag_sh[t] = (unsigned char)lt;

    if (tid == 0) {
        // tags[t-1] = bp[t][tags[t]], t = L-1 .. 1
        int tag = lt;
        for (int t = L - 1; t >= 1; --t) {
            tag = bp_sh[t * C_ + tag];
            tag_sh[t - 1] = (unsigned char)tag;
        }
    }
    __syncthreads();

    // ---------------- fused one-hot output ----------------
    float4* ob = (float4*)(out + (size_t)b * T_ * C_);
    for (int idx = tid; idx < T_ * ROW4; idx += NTH) {
        const int t  = idx / ROW4;
        const int qq = idx - t * ROW4;
        const int tg = tag_sh[t];
        const int base = qq * 4;
        float4 v;
        v.x = (tg == base + 0) ? 1.0f : 0.0f;
        v.y = (tg == base + 1) ? 1.0f : 0.0f;
        v.z = (tg == base + 2) ? 1.0f : 0.0f;
        v.w = (tg == base + 3) ? 1.0f : 0.0f;
        ob[idx] = v;
    }
}

extern "C" void kernel_launch(void* const* d_in, const int* in_sizes, int n_in,
                              void* d_out, int out_size)
{
    const float* pot    = (const float*)d_in[0];   // (B, T, C) float32
    const int*   slen   = (const int*)d_in[1];     // (B, 1)    int32
    const float* trans  = (const float*)d_in[2];   // (C, C)    float32
    float*       out    = (float*)d_out;           // (B, T, C) float32

    viterbi_kernel<<<B_, NTH>>>(pot, slen, trans, out);
}

// round 3
// speedup vs baseline: 1.4043x; 1.1354x over previous
#include <cuda_runtime.h>

#define B_ 1024
#define T_ 512
#define C_ 48
#define HALF 24            // i-elements per thread (2-way split of i)
#define NTH 96             // 48 states x 2 halves, 3 full warps
#define ROW4 (C_ / 4)      // 12 float4 per output row

// Viterbi decode: one block per batch element.
// Thread (j,h): j = tid>>1 (state column), h = tid&1 (half of i).
// Argmax via balanced tournament tree of (value,index) pairs — strict-'>'
// merges preserve first-index tie-break exactly. Pair halves combined with
// shfl_xor(1) using (value, then smaller-index) ordering.
__global__ void __launch_bounds__(NTH, 8)
viterbi_kernel(const float* __restrict__ pot,
               const int* __restrict__ seqlen,
               const float* __restrict__ trans,
               float* __restrict__ out)
{
    __shared__ unsigned char bp_sh[T_ * C_];          // 24576 B backpointers
    __shared__ unsigned char tag_sh[T_];              // decoded tags
    __shared__ __align__(16) float sc[2][C_];         // double-buffered score
    __shared__ int last_tag_sh;

    const int b   = blockIdx.x;
    const int tid = threadIdx.x;
    const int j   = tid >> 1;                         // state column 0..47
    const int h   = tid & 1;                          // half 0..1
    const int L   = seqlen[b];                        // 1 <= L < T_
    const float* potb = pot + (size_t)b * T_ * C_;

    // trans rows [h*24, h*24+24) of column j, in registers
    float tr[HALF];
#pragma unroll
    for (int k = 0; k < HALF; ++k) tr[k] = trans[(h * HALF + k) * C_ + j];

    if (h == 0) sc[0][j] = potb[j];                   // init score = potentials[:,0]
    __syncthreads();

    // ---------------- forward pass ----------------
    int cur = 0;
    float pn1 = (L > 1) ? potb[C_ + j] : 0.0f;        // prefetch t=1
    float pn2 = (L > 2) ? potb[2 * C_ + j] : 0.0f;    // prefetch t=2
    for (int t = 1; t < L; ++t) {
        const float potc = pn1;
        pn1 = pn2;
        if (t + 2 < L) pn2 = potb[(size_t)(t + 2) * C_ + j];

        // 24 independent adds
        const float4* sv = (const float4*)(sc[cur] + h * HALF);
        float v[HALF];
        int   bi[HALF];
#pragma unroll
        for (int i4 = 0; i4 < HALF / 4; ++i4) {
            const float4 q = sv[i4];
            v[i4 * 4 + 0] = q.x + tr[i4 * 4 + 0];
            v[i4 * 4 + 1] = q.y + tr[i4 * 4 + 1];
            v[i4 * 4 + 2] = q.z + tr[i4 * 4 + 2];
            v[i4 * 4 + 3] = q.w + tr[i4 * 4 + 3];
        }
#pragma unroll
        for (int k = 0; k < HALF; ++k) bi[k] = k;

        // balanced tournament: 5 levels, strict '>' keeps first-index ties
#pragma unroll
        for (int s = 1; s < HALF; s *= 2) {
#pragma unroll
            for (int k = 0; k + s < HALF; k += 2 * s) {
                if (v[k + s] > v[k]) { v[k] = v[k + s]; bi[k] = bi[k + s]; }
            }
        }
        const float best = v[0];
        const int   lbi  = bi[0] + h * HALF;

        // combine halves within the lane pair (value desc, then index asc)
        const float ob = __shfl_xor_sync(0xFFFFFFFFu, best, 1);
        const int   oi = __shfl_xor_sync(0xFFFFFFFFu, lbi,  1);
        const bool take_other = (ob > best) || (ob == best && oi < lbi);
        const float wbest = take_other ? ob : best;
        const int   wbi   = take_other ? oi : lbi;

        if (h == 0) {
            bp_sh[t * C_ + j] = (unsigned char)wbi;
            sc[cur ^ 1][j] = wbest + potc;
        }
        __syncthreads();
        cur ^= 1;
    }

    // ---------------- final argmax + backtrack ----------------
    if (tid == 0) {
        const float* fs = sc[cur];
        float best = fs[0];
        int bt = 0;
#pragma unroll
        for (int k = 1; k < C_; ++k) {
            float v = fs[k];
            if (v > best) { best = v; bt = k; }
        }
        last_tag_sh = bt;
    }
    __syncthreads();

    const int lt = last_tag_sh;
    // tags[L-1 .. T-1] == last_tag (identity backpointers past seq end)
    for (int t = L - 1 + tid; t < T_; t += NTH) tag_sh[t] = (unsigned char)lt;

    if (tid == 0) {
        // tags[t-1] = bp[t][tags[t]], t = L-1 .. 1
        int tag = lt;
        for (int t = L - 1; t >= 1; --t) {
            tag = bp_sh[t * C_ + tag];
            tag_sh[t - 1] = (unsigned char)tag;
        }
    }
    __syncthreads();

    // ---------------- fused one-hot output ----------------
    float4* ob4 = (float4*)(out + (size_t)b * T_ * C_);
    for (int idx = tid; idx < T_ * ROW4; idx += NTH) {
        const int t  = idx / ROW4;
        const int qq = idx - t * ROW4;
        const int tg = tag_sh[t];
        const int base = qq * 4;
        float4 w;
        w.x = (tg == base + 0) ? 1.0f : 0.0f;
        w.y = (tg == base + 1) ? 1.0f : 0.0f;
        w.z = (tg == base + 2) ? 1.0f : 0.0f;
        w.w = (tg == base + 3) ? 1.0f : 0.0f;
        ob4[idx] = w;
    }
}

extern "C" void kernel_launch(void* const* d_in, const int* in_sizes, int n_in,
                              void* d_out, int out_size)
{
    const float* pot    = (const float*)d_in[0];   // (B, T, C) float32
    const int*   slen   = (const int*)d_in[1];     // (B, 1)    int32
    const float* trans  = (const float*)d_in[2];   // (C, C)    float32
    float*       out    = (float*)d_out;           // (B, T, C) float32

    viterbi_kernel<<<B_, NTH>>>(pot, slen, trans, out);
}